// round 5
// baseline (speedup 1.0000x reference)
#include <cuda_runtime.h>

// Problem constants
#define BB 2
#define NN 2048
#define DIN 256
#define HH 8
#define DH 32
#define BH (BB*HH)            // 16
#define MSPLIT 8
#define MCHUNK (NN/MSPLIT)    // 256
#define TILE_M 64
#define NWORDS (NN/32)        // 64
#define SCALEF 0.17677669529663688f   // 1/sqrt(32)

typedef unsigned long long ull;

// ---------------- scratch (device globals; no allocations allowed) ----------
__device__ float    g_Q[BH*NN*DH];
__device__ float    g_K[BH*NN*DH];
__device__ float    g_V[BH*NN*DH];
__device__ unsigned g_bits[BB*NN*NWORDS];
__device__ float    g_pacc[MSPLIT*BH*NN*DH];
__device__ float    g_pl[MSPLIT*BH*NN];
__device__ float    g_attn[BB*NN*DIN];

// ---------------- f32x2 helpers (packed dual fp32 FMA, sm_100+) -------------
__device__ __forceinline__ ull pack2(float x, float y) {
    ull u; asm("mov.b64 %0, {%1, %2};" : "=l"(u) : "f"(x), "f"(y)); return u;
}
__device__ __forceinline__ float2 unpack2(ull u) {
    float2 v; asm("mov.b64 {%0, %1}, %2;" : "=f"(v.x), "=f"(v.y) : "l"(u)); return v;
}
__device__ __forceinline__ void ffma2(ull& d, ull a, ull b) {
    asm("fma.rn.f32x2 %0, %1, %2, %0;" : "+l"(d) : "l"(a), "l"(b));
}

// ---------------- kernel 0: adjacency -> bitmask ----------------------------
// one thread per 32 adjacency entries; grid covers exactly BB*NN*NWORDS words
__global__ __launch_bounds__(256) void adjbits_kernel(const float* __restrict__ adj) {
    int w = blockIdx.x * 256 + threadIdx.x;
    const float4* a = (const float4*)(adj + (size_t)w * 32);
    unsigned m = 0;
#pragma unroll
    for (int t = 0; t < 8; t++) {
        float4 v = a[t];
        m |= (v.x != 0.f ? 1u : 0u) << (4 * t + 0);
        m |= (v.y != 0.f ? 1u : 0u) << (4 * t + 1);
        m |= (v.z != 0.f ? 1u : 0u) << (4 * t + 2);
        m |= (v.w != 0.f ? 1u : 0u) << (4 * t + 3);
    }
    g_bits[w] = m;
}

// ---------------- GEMM: C[4096 x 64cols-per-block-col] = A(4096x256) @ W^T ---
// MODE 0: out[row*256+col] = acc + bias[col]          (output projection)
// MODE 1: scatter to [b,h,n,dh] layout, no bias       (Q/K/V projections)
template <int MODE>
__global__ __launch_bounds__(256) void gemm_kernel(const float* __restrict__ A,
                                                   const float* __restrict__ W,
                                                   const float* __restrict__ bias,
                                                   float* __restrict__ out) {
    __shared__ __align__(16) float As[16][68];
    __shared__ __align__(16) float Bs[16][68];
    const int tid = threadIdx.x;
    const int r0 = blockIdx.x * 64;
    const int c0 = blockIdx.y * 64;
    const int li = tid >> 2;
    const int lk = (tid & 3) * 4;
    const int i0 = (tid >> 4) * 4;
    const int j0 = (tid & 15) * 4;

    ull acc[4][2];
#pragma unroll
    for (int i = 0; i < 4; i++) { acc[i][0] = 0ull; acc[i][1] = 0ull; }

    for (int k0 = 0; k0 < 256; k0 += 16) {
        __syncthreads();
        float4 av = *(const float4*)(A + (size_t)(r0 + li) * 256 + k0 + lk);
        As[lk + 0][li] = av.x; As[lk + 1][li] = av.y;
        As[lk + 2][li] = av.z; As[lk + 3][li] = av.w;
        float4 wv = *(const float4*)(W + (size_t)(c0 + li) * 256 + k0 + lk);
        Bs[lk + 0][li] = wv.x; Bs[lk + 1][li] = wv.y;
        Bs[lk + 2][li] = wv.z; Bs[lk + 3][li] = wv.w;
        __syncthreads();
#pragma unroll
        for (int kk = 0; kk < 16; kk++) {
            float4 a = *(const float4*)&As[kk][i0];
            ulonglong2 bu = *(const ulonglong2*)&Bs[kk][j0];
            ull a0 = pack2(a.x, a.x), a1 = pack2(a.y, a.y);
            ull a2 = pack2(a.z, a.z), a3 = pack2(a.w, a.w);
            ffma2(acc[0][0], a0, bu.x); ffma2(acc[0][1], a0, bu.y);
            ffma2(acc[1][0], a1, bu.x); ffma2(acc[1][1], a1, bu.y);
            ffma2(acc[2][0], a2, bu.x); ffma2(acc[2][1], a2, bu.y);
            ffma2(acc[3][0], a3, bu.x); ffma2(acc[3][1], a3, bu.y);
        }
    }

#pragma unroll
    for (int ii = 0; ii < 4; ii++) {
        int row = r0 + i0 + ii;
#pragma unroll
        for (int jj = 0; jj < 2; jj++) {
            float2 v = unpack2(acc[ii][jj]);
            int c = c0 + j0 + jj * 2;
            if (MODE == 0) {
                out[(size_t)row * 256 + c]     = v.x + bias[c];
                out[(size_t)row * 256 + c + 1] = v.y + bias[c + 1];
            } else {
                int b_ = row >> 11, n = row & (NN - 1);
                int h = c >> 5, d = c & 31;
                size_t base = (((size_t)(b_ * HH + h)) * NN + n) * DH + d;
                out[base]     = v.x;
                out[base + 1] = v.y;
            }
        }
    }
}

// ---------------- attention: masked softmax(QK^T)V, m-split partials --------
// grid (NN/256, BH, MSPLIT), block 128; each thread owns 2 query rows.
// No running max needed: scores are bounded (|s| <= ~12), exp()/sum is exact
// softmax in fp32 range.
__global__ __launch_bounds__(128) void attn_kernel() {
    __shared__ __align__(16) float Ks[TILE_M * DH];
    __shared__ __align__(16) float Vs[TILE_M * DH];
    const int tid = threadIdx.x;
    const int bh = blockIdx.y;
    const int b = bh >> 3;
    const int n0 = blockIdx.x * 256 + tid * 2;
    const int msBase = blockIdx.z * MCHUNK;

    ull q0[16], q1[16], acc0[16], acc1[16];
    {
        const ulonglong2* p0 = (const ulonglong2*)(g_Q + ((size_t)bh * NN + n0) * DH);
        const ulonglong2* p1 = (const ulonglong2*)(g_Q + ((size_t)bh * NN + n0 + 1) * DH);
#pragma unroll
        for (int i = 0; i < 8; i++) {
            ulonglong2 t0 = p0[i]; q0[2 * i] = t0.x; q0[2 * i + 1] = t0.y;
            ulonglong2 t1 = p1[i]; q1[2 * i] = t1.x; q1[2 * i + 1] = t1.y;
        }
    }
#pragma unroll
    for (int i = 0; i < 16; i++) { acc0[i] = 0ull; acc1[i] = 0ull; }
    float l0 = 0.f, l1 = 0.f;

    const unsigned* bits0 = g_bits + ((size_t)b * NN + n0) * NWORDS;
    const unsigned* bits1 = bits0 + NWORDS;

    for (int t = 0; t < MCHUNK; t += TILE_M) {
        const int m0 = msBase + t;
        __syncthreads();
        {
            const float4* Kg = (const float4*)(g_K + ((size_t)bh * NN + m0) * DH);
            const float4* Vg = (const float4*)(g_V + ((size_t)bh * NN + m0) * DH);
            float4* Ks4 = (float4*)Ks;
            float4* Vs4 = (float4*)Vs;
#pragma unroll
            for (int i = 0; i < 4; i++) {
                Ks4[tid + 128 * i] = Kg[tid + 128 * i];
                Vs4[tid + 128 * i] = Vg[tid + 128 * i];
            }
        }
        __syncthreads();
        const int w = m0 >> 5;
#pragma unroll
        for (int half = 0; half < 2; half++) {
            const unsigned wa = bits0[w + half];
            const unsigned wb = bits1[w + half];
#pragma unroll 4
            for (int jj = 0; jj < 32; jj++) {
                const int j = half * 32 + jj;
                const ulonglong2* kr = (const ulonglong2*)(Ks + j * DH);
                ull d00 = 0, d01 = 0, d02 = 0, d03 = 0;
                ull d10 = 0, d11 = 0, d12 = 0, d13 = 0;
#pragma unroll
                for (int k = 0; k < 4; k++) {
                    ulonglong2 ka = kr[2 * k], kb = kr[2 * k + 1];
                    ffma2(d00, q0[4 * k + 0], ka.x); ffma2(d01, q0[4 * k + 1], ka.y);
                    ffma2(d02, q0[4 * k + 2], kb.x); ffma2(d03, q0[4 * k + 3], kb.y);
                    ffma2(d10, q1[4 * k + 0], ka.x); ffma2(d11, q1[4 * k + 1], ka.y);
                    ffma2(d12, q1[4 * k + 2], kb.x); ffma2(d13, q1[4 * k + 3], kb.y);
                }
                float2 e0 = unpack2(d00), e1 = unpack2(d01), e2 = unpack2(d02), e3 = unpack2(d03);
                float s0 = ((e0.x + e0.y) + (e1.x + e1.y)) + ((e2.x + e2.y) + (e3.x + e3.y));
                float2 f0 = unpack2(d10), f1 = unpack2(d11), f2 = unpack2(d12), f3 = unpack2(d13);
                float s1 = ((f0.x + f0.y) + (f1.x + f1.y)) + ((f2.x + f2.y) + (f3.x + f3.y));
                float p0 = ((wa >> jj) & 1u) ? __expf(s0 * SCALEF) : 0.f;
                float p1 = ((wb >> jj) & 1u) ? __expf(s1 * SCALEF) : 0.f;
                l0 += p0; l1 += p1;
                const ull pu0 = pack2(p0, p0);
                const ull pu1 = pack2(p1, p1);
                const ulonglong2* vr = (const ulonglong2*)(Vs + j * DH);
#pragma unroll
                for (int k = 0; k < 8; k++) {
                    ulonglong2 vv = vr[k];
                    ffma2(acc0[2 * k], pu0, vv.x); ffma2(acc0[2 * k + 1], pu0, vv.y);
                    ffma2(acc1[2 * k], pu1, vv.x); ffma2(acc1[2 * k + 1], pu1, vv.y);
                }
            }
        }
    }

    // write m-split partials
    {
        size_t base = (((size_t)blockIdx.z * BH + bh) * NN + n0) * DH;
        ulonglong2* pa = (ulonglong2*)(g_pacc + base);
        ulonglong2* pb = (ulonglong2*)(g_pacc + base + DH);
#pragma unroll
        for (int i = 0; i < 8; i++) {
            pa[i] = make_ulonglong2(acc0[2 * i], acc0[2 * i + 1]);
            pb[i] = make_ulonglong2(acc1[2 * i], acc1[2 * i + 1]);
        }
        size_t lbase = ((size_t)blockIdx.z * BH + bh) * NN + n0;
        g_pl[lbase]     = l0;
        g_pl[lbase + 1] = l1;
    }
}

// ---------------- combine m-split partials -> concat-head layout ------------
__global__ __launch_bounds__(256) void combine_kernel() {
    int idx = blockIdx.x * 256 + threadIdx.x;   // over BH*NN*DH = 2^20, exact grid
    int d = idx & 31;
    int n = (idx >> 5) & (NN - 1);
    int bh = idx >> 16;
    float a = 0.f, l = 0.f;
#pragma unroll
    for (int ms = 0; ms < MSPLIT; ms++) {
        a += g_pacc[(((size_t)ms * BH + bh) * NN + n) * DH + d];
        l += g_pl[((size_t)ms * BH + bh) * NN + n];
    }
    int b_ = bh >> 3, h = bh & 7;
    g_attn[((size_t)(b_ * NN + n)) * DIN + h * DH + d] = a / l;
}

// ---------------- launcher ---------------------------------------------------
extern "C" void kernel_launch(void* const* d_in, const int* in_sizes, int n_in,
                              void* d_out, int out_size) {
    const float* x   = (const float*)d_in[0];
    const float* adj = (const float*)d_in[1];
    const float* Wq  = (const float*)d_in[2];
    const float* Wk  = (const float*)d_in[3];
    const float* Wv  = (const float*)d_in[4];
    const float* Wo  = (const float*)d_in[5];
    const float* bo  = (const float*)d_in[6];
    float* out = (float*)d_out;
    (void)in_sizes; (void)n_in; (void)out_size;

    void *pQ, *pK, *pV, *pAttn;
    cudaGetSymbolAddress(&pQ, g_Q);
    cudaGetSymbolAddress(&pK, g_K);
    cudaGetSymbolAddress(&pV, g_V);
    cudaGetSymbolAddress(&pAttn, g_attn);

    adjbits_kernel<<<BB * NN * NWORDS / 256, 256>>>(adj);
    gemm_kernel<1><<<dim3(64, 4), 256>>>(x, Wq, nullptr, (float*)pQ);
    gemm_kernel<1><<<dim3(64, 4), 256>>>(x, Wk, nullptr, (float*)pK);
    gemm_kernel<1><<<dim3(64, 4), 256>>>(x, Wv, nullptr, (float*)pV);
    attn_kernel<<<dim3(NN / 256, BH, MSPLIT), 128>>>();
    combine_kernel<<<BH * NN * DH / 256, 256>>>();
    gemm_kernel<0><<<dim3(64, 4), 256>>>((const float*)pAttn, Wo, bo, out);
}